// round 14
// baseline (speedup 1.0000x reference)
#include <cuda_runtime.h>
#include <cstdint>

#define T_LEN 512
#define BATCH 2048
#define DIN   128
#define HID   16
#define NG    64            // 4 gates * HID
#define FANIN 144           // DIN + HID
#define CHUNK 32            // timesteps per sync chunk
#define NCHUNK (T_LEN / CHUNK)                  // 16
#define TILE_M 64
#define TILES_PER_CHUNK (CHUNK * BATCH / TILE_M)   // 1024
#define TOTAL_TILES (T_LEN * BATCH / TILE_M)       // 16384
#define RBLK  256           // recur blocks: 8 warps x 1 row = 8 rows each
#define GPERS 188           // persistent gemm blocks
#define NBLK  (RBLK + GPERS)   // 444 = 148 SMs x 3 blocks

// Scratch
__device__ float g_pre[(size_t)T_LEN * BATCH * NG];     // 256 MB
__device__ unsigned char g_Bh[NG * DIN * 2];            // B hi, [n][k] bf16
__device__ unsigned char g_Bl[NG * DIN * 2];            // B lo, [n][k] bf16
__device__ unsigned g_ticket;                           // gemm tile ticket
__device__ unsigned g_done[NCHUNK];                     // per-chunk tiles done

// ======================= helpers =======================
__device__ __forceinline__ uint32_t smem_u32(const void* p) {
    uint32_t a;
    asm("{ .reg .u64 t; cvta.to.shared.u64 t, %1; cvt.u32.u64 %0, t; }" : "=r"(a) : "l"(p));
    return a;
}
__device__ __forceinline__ unsigned ldacq(const unsigned* p) {
    unsigned v;
    asm volatile("ld.acquire.gpu.global.b32 %0, [%1];" : "=r"(v) : "l"(p));
    return v;
}
// cvt pair: LOWER half = first value argument
#define CVT2(result, a, b) \
    asm("cvt.rn.satfinite.bf16x2.f32 %0, %1, %2;" : "=r"(result) : "f"(b), "f"(a))

#define LDMX4(r0, r1, r2, r3, addr) \
    asm volatile("ldmatrix.sync.aligned.m8n8.x4.shared.b16 {%0,%1,%2,%3}, [%4];" \
        : "=r"(r0), "=r"(r1), "=r"(r2), "=r"(r3) : "r"(addr))

#define MMA16816(c0, c1, c2, c3, a0, a1, a2, a3, b0, b1) \
    asm volatile("mma.sync.aligned.m16n8k16.row.col.f32.bf16.bf16.f32 " \
        "{%0,%1,%2,%3}, {%4,%5,%6,%7}, {%8,%9}, {%0,%1,%2,%3};" \
        : "+f"(c0), "+f"(c1), "+f"(c2), "+f"(c3) \
        : "r"(a0), "r"(a1), "r"(a2), "r"(a3), "r"(b0), "r"(b1))

// ---------------- kernel 0: weights -> bf16 hi/lo; zero sync counters -------
__global__ void prep_kernel(const float* __restrict__ Wf, const float* __restrict__ Wi,
                            const float* __restrict__ Wu, const float* __restrict__ Wo) {
    int idx = blockIdx.x * blockDim.x + threadIdx.x;
    if (idx <= NCHUNK) {       // zero ticket + done[]
        if (idx == NCHUNK) g_ticket = 0u;
        else g_done[idx] = 0u;
    }
    if (idx >= NG * DIN) return;
    int n = idx >> 7;
    int k = idx & 127;
    int g = n >> 4, kh = n & 15;
    const float* W = (g == 0) ? Wf : (g == 1) ? Wi : (g == 2) ? Wu : Wo;
    float w = W[kh * FANIN + k];
    uint32_t hp; CVT2(hp, w, 0.f);
    float hf = __uint_as_float(hp << 16);
    uint32_t lp; CVT2(lp, w - hf, 0.f);
    *(unsigned short*)(g_Bh + (size_t)idx * 2) = (unsigned short)(hp & 0xffffu);
    *(unsigned short*)(g_Bl + (size_t)idx * 2) = (unsigned short)(lp & 0xffffu);
}

// ================== persistent fused kernel =================================
// blocks [0, RBLK): recurrence, 8 warps x 1 row/warp, 2 gates/lane,
//                   recurrent weights in REGISTERS (no per-step smem traffic).
// blocks [RBLK, NBLK): persistent gemm, 64-row tiles via g_ticket.
#define PADB 272
#define SM_AH 0
#define SM_AL 17408
#define SM_BH 34816
#define SM_BL 52224
#define GEMM_SMEM 69632

__global__ __launch_bounds__(256, 3) void fused_kernel(
    const float* __restrict__ x,
    const float* __restrict__ Wf, const float* __restrict__ bfv,
    const float* __restrict__ Wi, const float* __restrict__ biv,
    const float* __restrict__ Wu, const float* __restrict__ buv,
    const float* __restrict__ Wo, const float* __restrict__ bov,
    const float* __restrict__ thf, const float* __restrict__ thi,
    const float* __restrict__ thu, const float* __restrict__ tho,
    float* __restrict__ out) {

    extern __shared__ char smem[];
    const int tid = threadIdx.x;
    const int wid = tid >> 5;
    const int lane = tid & 31;

    if (blockIdx.x < RBLK) {
        // ===== recurrence: 1 row/warp, half0=(f,i), half1=(u,o), regs-only ====
        const int half = lane >> 4;
        const int kk   = lane & 15;
        const unsigned FULL = 0xffffffffu;
        const int r = blockIdx.x * 8 + wid;      // batch row

        const float* WA = half ? Wu : Wf;
        const float* WB = half ? Wo : Wi;
        float wa[HID], wb[HID];
#pragma unroll
        for (int j = 0; j < HID; j++) {
            wa[j] = WA[kk * FANIN + DIN + j];
            wb[j] = WB[kk * FANIN + DIN + j];
        }
        const float addA = half ? (buv[kk] + thu[kk]) : (bfv[kk] + thf[kk]);
        const float addB = half ? (bov[kk] + tho[kk]) : (biv[kk] + thi[kk]);
        const float scl = half ? 2.f : 1.f;

        const size_t outIdx = (size_t)r * HID + kk;
        float h = 0.f, c = 0.f;

        const size_t stride = (size_t)BATCH * NG;
        const float* prow = g_pre + (size_t)r * NG + half * 32 + kk;

        for (int ch = 0; ch < NCHUNK; ch++) {
            while (ldacq(&g_done[ch]) < TILES_PER_CHUNK) __nanosleep(64);

            const float* pbase = prow + (size_t)ch * CHUNK * stride;
            float bufA[4], bufB[4];
#pragma unroll
            for (int p = 0; p < 4; p++) {
                bufA[p] = pbase[(size_t)p * stride];
                bufB[p] = pbase[(size_t)p * stride + 16];
            }

#pragma unroll 4
            for (int t = 0; t < CHUNK; t++) {
                const int slot = t & 3;
                float zA = bufA[slot] + addA;
                float zB = bufB[slot] + addB;
                int tp = t + 4 < CHUNK ? t + 4 : CHUNK - 1;   // clamped prefetch
                bufA[slot] = pbase[(size_t)tp * stride];
                bufB[slot] = pbase[(size_t)tp * stride + 16];

                float hj[HID];
#pragma unroll
                for (int j = 0; j < HID; j++) hj[j] = __shfl_sync(FULL, h, j);
                {
                    float a0 = fmaf(hj[0], wa[0], fmaf(hj[1], wa[1],
                               fmaf(hj[2], wa[2], hj[3] * wa[3])));
                    float a1 = fmaf(hj[4], wa[4], fmaf(hj[5], wa[5],
                               fmaf(hj[6], wa[6], hj[7] * wa[7])));
                    float a2 = fmaf(hj[8], wa[8], fmaf(hj[9], wa[9],
                               fmaf(hj[10], wa[10], hj[11] * wa[11])));
                    float a3 = fmaf(hj[12], wa[12], fmaf(hj[13], wa[13],
                               fmaf(hj[14], wa[14], hj[15] * wa[15])));
                    zA += (a0 + a1) + (a2 + a3);
                    float b0 = fmaf(hj[0], wb[0], fmaf(hj[1], wb[1],
                               fmaf(hj[2], wb[2], hj[3] * wb[3])));
                    float b1 = fmaf(hj[4], wb[4], fmaf(hj[5], wb[5],
                               fmaf(hj[6], wb[6], hj[7] * wb[7])));
                    float b2 = fmaf(hj[8], wb[8], fmaf(hj[9], wb[9],
                               fmaf(hj[10], wb[10], hj[11] * wb[11])));
                    float b3 = fmaf(hj[12], wb[12], fmaf(hj[13], wb[13],
                               fmaf(hj[14], wb[14], hj[15] * wb[15])));
                    zB += (b0 + b1) + (b2 + b3);
                }
                float pA = __cosf(zA);
                float pB = __cosf(zB);
                // branch-free inclusive cumprod over each 16-lane half
#pragma unroll
                for (int d = 1; d < 16; d <<= 1) {
                    float uA = __shfl_up_sync(FULL, pA, d);
                    float uB = __shfl_up_sync(FULL, pB, d);
                    pA *= (kk >= d) ? uA : 1.0f;
                    pB *= (kk >= d) ? uB : 1.0f;
                }
                // uniform exp-form: half0 -> sigmoid, half1 -> tanh (scl=2)
                float eA = __expf(scl * pA);
                float qA = __fdividef(1.f, eA + 1.f);
                float sA = fmaf(-scl, qA, 1.f);
                float eB = __expf(pB);
                float sB = 1.f - __fdividef(1.f, eB + 1.f);
                // symmetric exchange: every lane reconstructs (f,i,g,o)
                float gx = __shfl_xor_sync(FULL, sA, 16);
                float ox = __shfl_xor_sync(FULL, sB, 16);
                float fE = half ? gx : sA;
                float iE = half ? ox : sB;
                float gE = half ? sA : gx;
                float oE = half ? sB : ox;
                c = fmaf(fE, c, iE * gE);
                float e2 = __expf(2.f * c);
                float tc = 1.f - __fdividef(2.f, e2 + 1.f);
                h = oE * tc;
                // duplicate-write identical values from both halves (benign)
                out[(size_t)(ch * CHUNK + t) * (BATCH * HID) + outIdx] = h;
            }
        }
        const size_t off = (size_t)T_LEN * BATCH * HID;
        out[off + outIdx] = h;
        out[off + (size_t)BATCH * HID + outIdx] = c;
        return;
    }

    // ================= persistent GEMM (64-row tiles, work-stealing) =========
    const uint32_t sb = smem_u32(smem);
    __shared__ unsigned s_tile;

    // stage B (hi/lo) once: 64 rows x 256 B into padded rows
    {
        const uint2* bhs = (const uint2*)g_Bh;
        const uint2* bls = (const uint2*)g_Bl;
#pragma unroll
        for (int i = tid; i < 2048; i += 256) {
            int row = i >> 5, chk = i & 31;
            uint32_t off = row * PADB + chk * 8;
            *(uint2*)(smem + SM_BH + off) = bhs[i];
            *(uint2*)(smem + SM_BL + off) = bls[i];
        }
    }

    const int wm = (wid & 3) * 16;        // 4 m-tiles of 16 rows
    const int wn = (wid >> 2) * 32;       // 2 n-halves of 32 cols
    const int rsel = lane & 15;
    const int ksel = (lane >> 4) * 16;
    const int rq = lane >> 2;
    const int cq = (lane & 3) * 2;

    for (;;) {
        if (tid == 0) s_tile = atomicAdd(&g_ticket, 1u);
        __syncthreads();
        unsigned tile = s_tile;
        if (tile >= TOTAL_TILES) break;
        const size_t m0 = (size_t)tile * TILE_M;

        // stage A: fp32 -> bf16 hi/lo split into padded rows (64 x 128)
        {
            const float4* xv = (const float4*)(x + m0 * DIN);
#pragma unroll 4
            for (int i = tid; i < 2048; i += 256) {
                int row = i >> 5;
                int c4  = i & 31;
                float4 v = xv[i];
                uint32_t h01, h23, l01, l23;
                CVT2(h01, v.x, v.y);
                CVT2(h23, v.z, v.w);
                float hx = __uint_as_float(h01 << 16);
                float hy = __uint_as_float(h01 & 0xffff0000u);
                float hz = __uint_as_float(h23 << 16);
                float hw = __uint_as_float(h23 & 0xffff0000u);
                CVT2(l01, v.x - hx, v.y - hy);
                CVT2(l23, v.z - hz, v.w - hw);
                uint32_t off = row * PADB + c4 * 8;
                *(uint2*)(smem + SM_AH + off) = make_uint2(h01, h23);
                *(uint2*)(smem + SM_AL + off) = make_uint2(l01, l23);
            }
        }
        __syncthreads();

        float acc[4][4];
#pragma unroll
        for (int nt = 0; nt < 4; nt++)
#pragma unroll
            for (int q = 0; q < 4; q++) acc[nt][q] = 0.f;

#pragma unroll
        for (int ks = 0; ks < 8; ks++) {
            const uint32_t kbyte = ks * 32 + ksel;
            uint32_t ah[4], al[4];
            {
                uint32_t rowb = (wm + rsel) * PADB + kbyte;
                LDMX4(ah[0], ah[1], ah[2], ah[3], sb + SM_AH + rowb);
                LDMX4(al[0], al[1], al[2], al[3], sb + SM_AL + rowb);
            }
            uint32_t bh[2][4], bl[2][4];
#pragma unroll
            for (int np = 0; np < 2; np++) {
                uint32_t rowb = (wn + np * 16 + rsel) * PADB + kbyte;
                LDMX4(bh[np][0], bh[np][1], bh[np][2], bh[np][3], sb + SM_BH + rowb);
                LDMX4(bl[np][0], bl[np][1], bl[np][2], bl[np][3], sb + SM_BL + rowb);
            }
#pragma unroll
            for (int p = 0; p < 3; p++) {
#pragma unroll
                for (int np = 0; np < 2; np++) {
#pragma unroll
                    for (int o = 0; o < 2; o++) {
                        float* cc = acc[np * 2 + o];
                        const uint32_t* aa = (p == 2) ? al : ah;
                        const uint32_t* bb = (p == 1) ? bl[np] : bh[np];
                        MMA16816(cc[0], cc[1], cc[2], cc[3],
                                 aa[0], aa[1], aa[2], aa[3], bb[o], bb[o + 2]);
                    }
                }
            }
        }

        // epilogue
        {
            size_t row = m0 + wm + rq;
#pragma unroll
            for (int nt = 0; nt < 4; nt++) {
                float* cc = acc[nt];
                int col = wn + nt * 8 + cq;
                *(float2*)(g_pre + row * NG + col)       = make_float2(cc[0], cc[1]);
                *(float2*)(g_pre + (row + 8) * NG + col) = make_float2(cc[2], cc[3]);
            }
        }
        __threadfence();           // pre stores visible before signaling
        __syncthreads();           // all threads' stores+fences done
        if (tid == 0) atomicAdd(&g_done[tile >> 10], 1u);   // 1024 tiles/chunk
        __syncthreads();           // protect s_tile and smem A restaging
    }
}

// ---------------- launch ----------------
extern "C" void kernel_launch(void* const* d_in, const int* in_sizes, int n_in,
                              void* d_out, int out_size) {
    const float* x   = (const float*)d_in[0];
    const float* Wf  = (const float*)d_in[1];
    const float* bfv = (const float*)d_in[2];
    const float* Wi  = (const float*)d_in[3];
    const float* biv = (const float*)d_in[4];
    const float* Wu  = (const float*)d_in[5];
    const float* buv = (const float*)d_in[6];
    const float* Wo  = (const float*)d_in[7];
    const float* bov = (const float*)d_in[8];
    const float* thf = (const float*)d_in[9];
    const float* thi = (const float*)d_in[10];
    const float* thu = (const float*)d_in[11];
    const float* tho = (const float*)d_in[12];
    float* out = (float*)d_out;

    cudaFuncSetAttribute(fused_kernel,
                         cudaFuncAttributeMaxDynamicSharedMemorySize, GEMM_SMEM);

    prep_kernel<<<16, 512>>>(Wf, Wi, Wu, Wo);
    fused_kernel<<<NBLK, 256, GEMM_SMEM>>>(
        x, Wf, bfv, Wi, biv, Wu, buv, Wo, bov,
        thf, thi, thu, tho, out);
}

// round 15
// speedup vs baseline: 1.2039x; 1.2039x over previous
#include <cuda_runtime.h>
#include <cstdint>

#define T_LEN 512
#define BATCH 2048
#define DIN   128
#define HID   16
#define NG    64            // 4 gates * HID
#define FANIN 144           // DIN + HID
#define CHUNK 32            // timesteps per sync chunk
#define NCHUNK (T_LEN / CHUNK)                  // 16
#define TILES_PER_CHUNK (CHUNK * BATCH / 128)   // 512
#define TOTAL_TILES (T_LEN * BATCH / 128)       // 8192
#define RBLK  128           // recur blocks (16 warps = 16 batch rows each)
#define GPERS 160           // persistent gemm blocks
#define NBLK  (RBLK + GPERS)

// Scratch
__device__ float g_pre[(size_t)T_LEN * BATCH * NG];     // 256 MB
__device__ unsigned char g_Bh[NG * DIN * 2];            // B hi, [n][k] bf16
__device__ unsigned char g_Bl[NG * DIN * 2];            // B lo, [n][k] bf16
__device__ unsigned g_ticket;                           // gemm tile ticket
__device__ unsigned g_done[NCHUNK];                     // per-chunk tiles done

// ======================= helpers =======================
__device__ __forceinline__ uint32_t smem_u32(const void* p) {
    uint32_t a;
    asm("{ .reg .u64 t; cvta.to.shared.u64 t, %1; cvt.u32.u64 %0, t; }" : "=r"(a) : "l"(p));
    return a;
}
__device__ __forceinline__ unsigned ldacq(const unsigned* p) {
    unsigned v;
    asm volatile("ld.acquire.gpu.global.b32 %0, [%1];" : "=r"(v) : "l"(p));
    return v;
}
// cvt pair: LOWER half = first value argument
#define CVT2(result, a, b) \
    asm("cvt.rn.satfinite.bf16x2.f32 %0, %1, %2;" : "=r"(result) : "f"(b), "f"(a))

#define LDMX4(r0, r1, r2, r3, addr) \
    asm volatile("ldmatrix.sync.aligned.m8n8.x4.shared.b16 {%0,%1,%2,%3}, [%4];" \
        : "=r"(r0), "=r"(r1), "=r"(r2), "=r"(r3) : "r"(addr))

#define MMA16816(c0, c1, c2, c3, a0, a1, a2, a3, b0, b1) \
    asm volatile("mma.sync.aligned.m16n8k16.row.col.f32.bf16.bf16.f32 " \
        "{%0,%1,%2,%3}, {%4,%5,%6,%7}, {%8,%9}, {%0,%1,%2,%3};" \
        : "+f"(c0), "+f"(c1), "+f"(c2), "+f"(c3) \
        : "r"(a0), "r"(a1), "r"(a2), "r"(a3), "r"(b0), "r"(b1))

// ---------------- kernel 0: weights -> bf16 hi/lo; zero sync counters -------
__global__ void prep_kernel(const float* __restrict__ Wf, const float* __restrict__ Wi,
                            const float* __restrict__ Wu, const float* __restrict__ Wo) {
    int idx = blockIdx.x * blockDim.x + threadIdx.x;
    if (idx <= NCHUNK) {       // zero ticket + done[]
        if (idx == NCHUNK) g_ticket = 0u;
        else g_done[idx] = 0u;
    }
    if (idx >= NG * DIN) return;
    int n = idx >> 7;
    int k = idx & 127;
    int g = n >> 4, kh = n & 15;
    const float* W = (g == 0) ? Wf : (g == 1) ? Wi : (g == 2) ? Wu : Wo;
    float w = W[kh * FANIN + k];
    uint32_t hp; CVT2(hp, w, 0.f);
    float hf = __uint_as_float(hp << 16);
    uint32_t lp; CVT2(lp, w - hf, 0.f);
    *(unsigned short*)(g_Bh + (size_t)idx * 2) = (unsigned short)(hp & 0xffffu);
    *(unsigned short*)(g_Bl + (size_t)idx * 2) = (unsigned short)(lp & 0xffffu);
}

// ================== persistent fused kernel =================================
// blocks [0, RBLK): recurrence, 16 warps x 1 row/warp, 2 gates/lane,
//   recurrent weights in REGISTERS (interleaved shfl+fma dot keeps regs <= 64).
// blocks [RBLK, NBLK): persistent gemm, 128-row tiles via g_ticket.
#define PADB 272
#define SM_AH 0
#define SM_AL 34816
#define SM_BH 69632
#define SM_BL 87040
#define GEMM_SMEM 104448

__global__ __launch_bounds__(512, 2) void fused_kernel(
    const float* __restrict__ x,
    const float* __restrict__ Wf, const float* __restrict__ bfv,
    const float* __restrict__ Wi, const float* __restrict__ biv,
    const float* __restrict__ Wu, const float* __restrict__ buv,
    const float* __restrict__ Wo, const float* __restrict__ bov,
    const float* __restrict__ thf, const float* __restrict__ thi,
    const float* __restrict__ thu, const float* __restrict__ tho,
    float* __restrict__ out) {

    extern __shared__ char smem[];
    const int tid = threadIdx.x;
    const int wid = tid >> 5;
    const int lane = tid & 31;

    if (blockIdx.x < RBLK) {
        // ===== recurrence: 1 row/warp, half0=(f,i), half1=(u,o), regs-only ====
        const int half = lane >> 4;
        const int kk   = lane & 15;
        const unsigned FULL = 0xffffffffu;
        const int r = blockIdx.x * 16 + wid;     // batch row

        const float* WA = half ? Wu : Wf;
        const float* WB = half ? Wo : Wi;
        float wa[HID], wb[HID];
#pragma unroll
        for (int j = 0; j < HID; j++) {
            wa[j] = WA[kk * FANIN + DIN + j];
            wb[j] = WB[kk * FANIN + DIN + j];
        }
        const float addA = half ? (buv[kk] + thu[kk]) : (bfv[kk] + thf[kk]);
        const float addB = half ? (bov[kk] + tho[kk]) : (biv[kk] + thi[kk]);
        const float scl = half ? 2.f : 1.f;

        const size_t outIdx = (size_t)r * HID + kk;
        float h = 0.f, c = 0.f;

        const size_t stride = (size_t)BATCH * NG;
        const float* prow = g_pre + (size_t)r * NG + half * 32 + kk;

        for (int ch = 0; ch < NCHUNK; ch++) {
            while (ldacq(&g_done[ch]) < TILES_PER_CHUNK) __nanosleep(64);

            const float* pbase = prow + (size_t)ch * CHUNK * stride;
            float bufA[4], bufB[4];
#pragma unroll
            for (int p = 0; p < 4; p++) {
                bufA[p] = pbase[(size_t)p * stride];
                bufB[p] = pbase[(size_t)p * stride + 16];
            }

#pragma unroll 4
            for (int t = 0; t < CHUNK; t++) {
                const int slot = t & 3;
                float zA = bufA[slot] + addA;
                float zB = bufB[slot] + addB;
                int tp = t + 4 < CHUNK ? t + 4 : CHUNK - 1;   // clamped prefetch
                bufA[slot] = pbase[(size_t)tp * stride];
                bufB[slot] = pbase[(size_t)tp * stride + 16];

                // interleaved h-broadcast + dot: <=4 live hj at a time
#pragma unroll
                for (int j = 0; j < HID; j += 4) {
                    float h0 = __shfl_sync(FULL, h, j);
                    float h1 = __shfl_sync(FULL, h, j + 1);
                    float h2 = __shfl_sync(FULL, h, j + 2);
                    float h3 = __shfl_sync(FULL, h, j + 3);
                    zA = fmaf(h0, wa[j],     zA);
                    zA = fmaf(h1, wa[j + 1], zA);
                    zA = fmaf(h2, wa[j + 2], zA);
                    zA = fmaf(h3, wa[j + 3], zA);
                    zB = fmaf(h0, wb[j],     zB);
                    zB = fmaf(h1, wb[j + 1], zB);
                    zB = fmaf(h2, wb[j + 2], zB);
                    zB = fmaf(h3, wb[j + 3], zB);
                }

                float pA = __cosf(zA);
                float pB = __cosf(zB);
                // branch-free inclusive cumprod over each 16-lane half
#pragma unroll
                for (int d = 1; d < 16; d <<= 1) {
                    float uA = __shfl_up_sync(FULL, pA, d);
                    float uB = __shfl_up_sync(FULL, pB, d);
                    pA *= (kk >= d) ? uA : 1.0f;
                    pB *= (kk >= d) ? uB : 1.0f;
                }
                // uniform exp-form: half0 -> sigmoid, half1 -> tanh (scl=2)
                float eA = __expf(scl * pA);
                float qA = __fdividef(1.f, eA + 1.f);
                float sA = fmaf(-scl, qA, 1.f);
                float eB = __expf(pB);
                float sB = 1.f - __fdividef(1.f, eB + 1.f);
                // symmetric exchange: every lane reconstructs (f,i,g,o)
                float gx = __shfl_xor_sync(FULL, sA, 16);
                float ox = __shfl_xor_sync(FULL, sB, 16);
                float fE = half ? gx : sA;
                float iE = half ? ox : sB;
                float gE = half ? sA : gx;
                float oE = half ? sB : ox;
                c = fmaf(fE, c, iE * gE);
                float e2 = __expf(2.f * c);
                float tc = 1.f - __fdividef(2.f, e2 + 1.f);
                h = oE * tc;
                // duplicate-write identical values from both halves (benign)
                out[(size_t)(ch * CHUNK + t) * (BATCH * HID) + outIdx] = h;
            }
        }
        const size_t off = (size_t)T_LEN * BATCH * HID;
        out[off + outIdx] = h;
        out[off + (size_t)BATCH * HID + outIdx] = c;
        return;
    }

    // ================= persistent GEMM (128-row tiles, work-stealing) ========
    const uint32_t sb = smem_u32(smem);
    __shared__ unsigned s_tile;

    // stage B (hi/lo) once: 64 rows x 256 B into padded rows
    {
        const uint2* bhs = (const uint2*)g_Bh;
        const uint2* bls = (const uint2*)g_Bl;
#pragma unroll
        for (int i = tid; i < 2048; i += 512) {
            int row = i >> 5, chk = i & 31;
            uint32_t off = row * PADB + chk * 8;
            *(uint2*)(smem + SM_BH + off) = bhs[i];
            *(uint2*)(smem + SM_BL + off) = bls[i];
        }
    }

    const int wm = ((tid >> 5) & 7) * 16;
    const int wn = ((tid >> 5) >> 3) * 32;
    const int rsel = lane & 15;
    const int ksel = (lane >> 4) * 16;
    const int rq = lane >> 2;
    const int cq = (lane & 3) * 2;

    for (;;) {
        if (tid == 0) s_tile = atomicAdd(&g_ticket, 1u);
        __syncthreads();
        unsigned tile = s_tile;
        if (tile >= TOTAL_TILES) break;
        const size_t m0 = (size_t)tile * 128;

        // stage A: fp32 -> bf16 hi/lo split into padded rows (128 x 128)
        {
            const float4* xv = (const float4*)(x + m0 * DIN);
#pragma unroll 4
            for (int i = tid; i < 4096; i += 512) {
                int row = i >> 5;
                int c4  = i & 31;
                float4 v = xv[i];
                uint32_t h01, h23, l01, l23;
                CVT2(h01, v.x, v.y);
                CVT2(h23, v.z, v.w);
                float hx = __uint_as_float(h01 << 16);
                float hy = __uint_as_float(h01 & 0xffff0000u);
                float hz = __uint_as_float(h23 << 16);
                float hw = __uint_as_float(h23 & 0xffff0000u);
                CVT2(l01, v.x - hx, v.y - hy);
                CVT2(l23, v.z - hz, v.w - hw);
                uint32_t off = row * PADB + c4 * 8;
                *(uint2*)(smem + SM_AH + off) = make_uint2(h01, h23);
                *(uint2*)(smem + SM_AL + off) = make_uint2(l01, l23);
            }
        }
        __syncthreads();

        float acc[4][4];
#pragma unroll
        for (int nt = 0; nt < 4; nt++)
#pragma unroll
            for (int q = 0; q < 4; q++) acc[nt][q] = 0.f;

#pragma unroll
        for (int ks = 0; ks < 8; ks++) {
            const uint32_t kbyte = ks * 32 + ksel;
            uint32_t ah[4], al[4];
            {
                uint32_t rowb = (wm + rsel) * PADB + kbyte;
                LDMX4(ah[0], ah[1], ah[2], ah[3], sb + SM_AH + rowb);
                LDMX4(al[0], al[1], al[2], al[3], sb + SM_AL + rowb);
            }
            uint32_t bh[2][4], bl[2][4];
#pragma unroll
            for (int np = 0; np < 2; np++) {
                uint32_t rowb = (wn + np * 16 + rsel) * PADB + kbyte;
                LDMX4(bh[np][0], bh[np][1], bh[np][2], bh[np][3], sb + SM_BH + rowb);
                LDMX4(bl[np][0], bl[np][1], bl[np][2], bl[np][3], sb + SM_BL + rowb);
            }
#pragma unroll
            for (int p = 0; p < 3; p++) {
#pragma unroll
                for (int np = 0; np < 2; np++) {
#pragma unroll
                    for (int o = 0; o < 2; o++) {
                        float* cc = acc[np * 2 + o];
                        const uint32_t* aa = (p == 2) ? al : ah;
                        const uint32_t* bb = (p == 1) ? bl[np] : bh[np];
                        MMA16816(cc[0], cc[1], cc[2], cc[3],
                                 aa[0], aa[1], aa[2], aa[3], bb[o], bb[o + 2]);
                    }
                }
            }
        }

        // epilogue
        {
            size_t row = m0 + wm + rq;
#pragma unroll
            for (int nt = 0; nt < 4; nt++) {
                float* cc = acc[nt];
                int col = wn + nt * 8 + cq;
                *(float2*)(g_pre + row * NG + col)       = make_float2(cc[0], cc[1]);
                *(float2*)(g_pre + (row + 8) * NG + col) = make_float2(cc[2], cc[3]);
            }
        }
        __threadfence();           // pre stores visible before signaling
        __syncthreads();           // all threads' stores+fences done
        if (tid == 0) atomicAdd(&g_done[tile >> 9], 1u);   // 512 tiles/chunk
        __syncthreads();           // protect s_tile and smem A restaging
    }
}

// ---------------- launch ----------------
extern "C" void kernel_launch(void* const* d_in, const int* in_sizes, int n_in,
                              void* d_out, int out_size) {
    const float* x   = (const float*)d_in[0];
    const float* Wf  = (const float*)d_in[1];
    const float* bfv = (const float*)d_in[2];
    const float* Wi  = (const float*)d_in[3];
    const float* biv = (const float*)d_in[4];
    const float* Wu  = (const float*)d_in[5];
    const float* buv = (const float*)d_in[6];
    const float* Wo  = (const float*)d_in[7];
    const float* bov = (const float*)d_in[8];
    const float* thf = (const float*)d_in[9];
    const float* thi = (const float*)d_in[10];
    const float* thu = (const float*)d_in[11];
    const float* tho = (const float*)d_in[12];
    float* out = (float*)d_out;

    cudaFuncSetAttribute(fused_kernel,
                         cudaFuncAttributeMaxDynamicSharedMemorySize, GEMM_SMEM);

    prep_kernel<<<16, 512>>>(Wf, Wi, Wu, Wo);
    fused_kernel<<<NBLK, 512, GEMM_SMEM>>>(
        x, Wf, bfv, Wi, biv, Wu, buv, Wo, bov,
        thf, thi, thu, tho, out);
}